// round 3
// baseline (speedup 1.0000x reference)
#include <cuda_runtime.h>
#include <math.h>

// Problem constants (fixed by the dataset)
#define NN   50000   // nodes
#define EE   800000  // edges
#define CC   5000    // clusters
#define DD   128     // in_features
#define OO   40      // out_features

#define FULL_MASK 0xffffffffu

// -------- scratch (no allocation allowed -> __device__ globals) ----------
// NOTE: these are ONLY referenced from device code. Passing a __device__
// symbol as a kernel argument from host code silently yields the host
// shadow address (dereferenceable via ATS on GB300) -> data corruption.
__device__ int           g_deg[NN];
__device__ float         g_dinv[NN];
__device__ unsigned char g_is_rep[NN];
__device__ unsigned char g_needed[NN];
__device__ float         g_z0[NN * OO];   // projected features
__device__ float         g_z1[NN * OO];   // after hop 1
__device__ float         g_z2[NN * OO];   // after hop 2
__device__ float         g_lsm[CC * OO];  // per-cluster log-softmax

// -------- kernels --------------------------------------------------------

// deg = 1 (self loop), clear masks
__global__ void k_init(void) {
    int i = blockIdx.x * blockDim.x + threadIdx.x;
    if (i >= NN) return;
    g_deg[i] = 1;
    g_is_rep[i] = 0;
    g_needed[i] = 0;
}

// count in-degree over edges
__global__ void k_degree(const int* __restrict__ dst) {
    int e = blockIdx.x * blockDim.x + threadIdx.x;
    if (e >= EE) return;
    atomicAdd(&g_deg[dst[e]], 1);
}

// mark representative nodes (also needed for their hop-2 self loop)
__global__ void k_mark_rep(const int* __restrict__ rep_idx) {
    int c = blockIdx.x * blockDim.x + threadIdx.x;
    if (c >= CC) return;
    int r = rep_idx[c];
    g_is_rep[r] = 1;
    g_needed[r] = 1;
}

// mark hop-1 "needed" set: sources of edges whose dst is a rep node
__global__ void k_mark_needed(const int* __restrict__ src, const int* __restrict__ dst) {
    int e = blockIdx.x * blockDim.x + threadIdx.x;
    if (e >= EE) return;
    if (g_is_rep[dst[e]]) g_needed[src[e]] = 1;
}

__global__ void k_dinv(void) {
    int i = blockIdx.x * blockDim.x + threadIdx.x;
    if (i >= NN) return;
    g_dinv[i] = rsqrtf((float)g_deg[i]);
}

// z0 = x @ W^T   (x:[N,128], W:[40,128])
// block = 256 threads, 32 nodes/block; thread = (node_lane = tid>>3, chunk = tid&7)
// each thread computes 5 outputs (o = chunk*5 + j) for its node.
__global__ void k_gemm(const float* __restrict__ x, const float* __restrict__ W) {
    __shared__ float ws[OO * 132];   // stride 132 floats (16B aligned, conflict-avoiding)
    int tid = threadIdx.x;
    for (int idx = tid; idx < OO * DD; idx += 256) {
        int o = idx >> 7, d = idx & 127;
        ws[o * 132 + d] = W[idx];
    }
    __syncthreads();

    int ln = tid >> 3;         // 0..31 node within block
    int chunk = tid & 7;       // 0..7 -> outputs chunk*5 .. chunk*5+4
    int node = blockIdx.x * 32 + ln;
    if (node >= NN) return;

    const float4* xr = reinterpret_cast<const float4*>(x + (size_t)node * DD);
    float acc[5] = {0.f, 0.f, 0.f, 0.f, 0.f};
    int obase = chunk * 5;
#pragma unroll
    for (int d4 = 0; d4 < DD / 4; d4++) {
        float4 xv = xr[d4];
#pragma unroll
        for (int j = 0; j < 5; j++) {
            float4 wv = *reinterpret_cast<const float4*>(&ws[(obase + j) * 132 + d4 * 4]);
            acc[j] += xv.x * wv.x + xv.y * wv.y + xv.z * wv.z + xv.w * wv.w;
        }
    }
#pragma unroll
    for (int j = 0; j < 5; j++)
        g_z0[(size_t)node * OO + obase + j] = acc[j];
}

// z_out[i] = dinv[i]^2 * z_in[i]   (self-loop term; also initializes z_out)
// HOP selects buffers at compile time so globals are referenced device-side.
template <int HOP>
__global__ void k_selfloop(void) {
    const float* zin  = (HOP == 1) ? g_z0 : g_z1;
    float*       zout = (HOP == 1) ? g_z1 : g_z2;
    int idx = blockIdx.x * blockDim.x + threadIdx.x;
    if (idx >= NN * OO) return;
    int n = idx / OO;
    float di = g_dinv[n];
    zout[idx] = di * di * zin[idx];
}

// one warp per edge: z_out[dst] += dinv[src]*dinv[dst] * z_in[src], filtered by mask[dst]
template <int HOP>
__global__ void k_hop(const int* __restrict__ src, const int* __restrict__ dst) {
    const float*         zin  = (HOP == 1) ? g_z0 : g_z1;
    float*               zout = (HOP == 1) ? g_z1 : g_z2;
    const unsigned char* filt = (HOP == 1) ? g_needed : g_is_rep;

    int e = (blockIdx.x * blockDim.x + threadIdx.x) >> 5;
    if (e >= EE) return;
    int lane = threadIdx.x & 31;
    int s = __ldg(&src[e]);          // warp-uniform -> L1 broadcast
    int d = __ldg(&dst[e]);
    if (!filt[d]) return;
    float coeff = g_dinv[s] * g_dinv[d];
    const float* zi = zin + (size_t)s * OO;
    float*       zo = zout + (size_t)d * OO;
    atomicAdd(&zo[lane], coeff * zi[lane]);                 // f = 0..31
    if (lane < OO - 32)
        atomicAdd(&zo[32 + lane], coeff * zi[32 + lane]);   // f = 32..39
}

// one warp per cluster: gather rep row, + b, log_softmax over 40
__global__ void k_logsoftmax(const int* __restrict__ rep_idx, const float* __restrict__ b) {
    int c = (blockIdx.x * blockDim.x + threadIdx.x) >> 5;
    if (c >= CC) return;
    int lane = threadIdx.x & 31;
    int r = rep_idx[c];
    const float* zr = g_z2 + (size_t)r * OO;
    float v1 = zr[lane] + b[lane];
    float v2 = (lane < OO - 32) ? (zr[32 + lane] + b[32 + lane]) : -INFINITY;
    float m = fmaxf(v1, v2);
#pragma unroll
    for (int off = 16; off > 0; off >>= 1)
        m = fmaxf(m, __shfl_xor_sync(FULL_MASK, m, off));
    float s = expf(v1 - m) + ((lane < OO - 32) ? expf(v2 - m) : 0.f);
#pragma unroll
    for (int off = 16; off > 0; off >>= 1)
        s += __shfl_xor_sync(FULL_MASK, s, off);
    float ls = m + logf(s);
    g_lsm[(size_t)c * OO + lane] = v1 - ls;
    if (lane < OO - 32)
        g_lsm[(size_t)c * OO + 32 + lane] = v2 - ls;
}

// out[n][f] = lsm[cluster_index[n]][f]
__global__ void k_scatter(const int* __restrict__ cluster_index, float* __restrict__ out) {
    int idx = blockIdx.x * blockDim.x + threadIdx.x;
    if (idx >= NN * OO) return;
    int n = idx / OO;
    int f = idx - n * OO;
    out[idx] = g_lsm[(size_t)cluster_index[n] * OO + f];
}

// -------- launch ---------------------------------------------------------
extern "C" void kernel_launch(void* const* d_in, const int* in_sizes, int n_in,
                              void* d_out, int out_size) {
    const float* x       = (const float*)d_in[0];            // [N,128]
    const int*   eidx    = (const int*)d_in[1];              // [2,E] row-major
    const int*   cluster = (const int*)d_in[2];              // [N]
    const int*   rep_idx = (const int*)d_in[3];              // [C]
    const float* W       = (const float*)d_in[4];            // [40,128]
    const float* b       = (const float*)d_in[5];            // [40]
    float*       out     = (float*)d_out;                    // [N,40]

    const int* src = eidx;        // edge_index[0]
    const int* dst = eidx + EE;   // edge_index[1]

    const int T = 256;
    dim3 bN((NN + T - 1) / T);
    dim3 bE((EE + T - 1) / T);
    dim3 bC((CC + T - 1) / T);
    dim3 bNF((NN * OO + T - 1) / T);
    dim3 bEdgeWarp((EE * 32 + T - 1) / T);   // warp per edge
    dim3 bClWarp((CC * 32 + T - 1) / T);     // warp per cluster
    dim3 bGemm((NN + 31) / 32);

    k_init<<<bN, T>>>();
    k_degree<<<bE, T>>>(dst);
    k_mark_rep<<<bC, T>>>(rep_idx);
    k_mark_needed<<<bE, T>>>(src, dst);
    k_dinv<<<bN, T>>>();
    k_gemm<<<bGemm, T>>>(x, W);
    // hop 1: z0 -> z1 (filtered to nodes feeding hop 2)
    k_selfloop<1><<<bNF, T>>>();
    k_hop<1><<<bEdgeWarp, T>>>(src, dst);
    // hop 2: z1 -> z2 (only rep destinations matter)
    k_selfloop<2><<<bNF, T>>>();
    k_hop<2><<<bEdgeWarp, T>>>(src, dst);
    // compress + linear bias + log_softmax, then scatter to all nodes
    k_logsoftmax<<<bClWarp, T>>>(rep_idx, b);
    k_scatter<<<bNF, T>>>(cluster, out);
}

// round 4
// speedup vs baseline: 1.0528x; 1.0528x over previous
#include <cuda_runtime.h>
#include <math.h>

// Problem constants (fixed by the dataset)
#define NN   50000   // nodes
#define EE   800000  // edges
#define CC   5000    // clusters
#define DD   128     // in_features
#define OO   40      // out_features

#define FULL_MASK 0xffffffffu
#define SCAN_T 1024
#define SCAN_CHUNK ((NN + SCAN_T - 1) / SCAN_T)   // 49

// -------- scratch (__device__ globals; only referenced from device code) --
__device__ int           g_cnt[NN];        // in-edge count (no self loop)
__device__ int           g_off[NN + 1];    // CSC offsets
__device__ int           g_pos[NN];        // placement cursor for fill
__device__ int           g_csc_src[EE];    // dst-sorted source indices
__device__ float         g_dinv[NN];
__device__ unsigned char g_is_rep[NN];
__device__ unsigned char g_needed[NN];
__device__ float         g_z0[NN * OO];    // projected features
__device__ float         g_z1[NN * OO];    // after hop 1
__device__ float         g_lsm[CC * OO];   // per-cluster log-softmax

// -------- kernels --------------------------------------------------------

__global__ void k_init(void) {
    int i = blockIdx.x * blockDim.x + threadIdx.x;
    if (i >= NN) return;
    g_cnt[i] = 0;
    g_is_rep[i] = 0;
    g_needed[i] = 0;
}

__global__ void k_mark_rep(const int* __restrict__ rep_idx) {
    int c = blockIdx.x * blockDim.x + threadIdx.x;
    if (c >= CC) return;
    int r = rep_idx[c];
    g_is_rep[r] = 1;
    g_needed[r] = 1;
}

// fused: count in-edges per dst + mark hop-1 needed set (srcs feeding reps)
__global__ void k_count_mark(const int* __restrict__ src, const int* __restrict__ dst) {
    int e = blockIdx.x * blockDim.x + threadIdx.x;
    if (e >= EE) return;
    int d = dst[e];
    atomicAdd(&g_cnt[d], 1);
    if (g_is_rep[d]) g_needed[src[e]] = 1;
}

// single-block exclusive prefix scan of g_cnt -> g_off/g_pos; also dinv.
__global__ void k_scan(void) {
    __shared__ int sh[SCAN_T];
    int tid = threadIdx.x;
    int base = tid * SCAN_CHUNK;
    int local = 0;
#pragma unroll 4
    for (int j = 0; j < SCAN_CHUNK; j++) {
        int i = base + j;
        if (i < NN) local += g_cnt[i];
    }
    sh[tid] = local;
    __syncthreads();
    // Hillis-Steele inclusive scan
    for (int off = 1; off < SCAN_T; off <<= 1) {
        int v = (tid >= off) ? sh[tid - off] : 0;
        __syncthreads();
        sh[tid] += v;
        __syncthreads();
    }
    int run = sh[tid] - local;   // exclusive prefix for this chunk
    for (int j = 0; j < SCAN_CHUNK; j++) {
        int i = base + j;
        if (i < NN) {
            int c = g_cnt[i];
            g_off[i] = run;
            g_pos[i] = run;
            g_dinv[i] = rsqrtf((float)(c + 1));
            run += c;
        }
    }
    if (tid == SCAN_T - 1) g_off[NN] = sh[SCAN_T - 1];
}

// scatter edges into dst-sorted buckets (order within bucket is arbitrary)
__global__ void k_fill(const int* __restrict__ src, const int* __restrict__ dst) {
    int e = blockIdx.x * blockDim.x + threadIdx.x;
    if (e >= EE) return;
    int p = atomicAdd(&g_pos[dst[e]], 1);
    g_csc_src[p] = src[e];
}

// z0 = x @ W^T   (x:[N,128], W:[40,128])
__global__ void k_gemm(const float* __restrict__ x, const float* __restrict__ W) {
    __shared__ float ws[OO * 132];   // stride 132 floats (16B aligned, conflict-free)
    int tid = threadIdx.x;
    for (int idx = tid; idx < OO * DD; idx += 256) {
        int o = idx >> 7, d = idx & 127;
        ws[o * 132 + d] = W[idx];
    }
    __syncthreads();

    int ln = tid >> 3;         // node within block (0..31)
    int chunk = tid & 7;       // output chunk (0..7) -> outputs chunk*5..+4
    int node = blockIdx.x * 32 + ln;
    if (node >= NN) return;

    const float4* xr = reinterpret_cast<const float4*>(x + (size_t)node * DD);
    float acc[5] = {0.f, 0.f, 0.f, 0.f, 0.f};
    int obase = chunk * 5;
#pragma unroll
    for (int d4 = 0; d4 < DD / 4; d4++) {
        float4 xv = xr[d4];
#pragma unroll
        for (int j = 0; j < 5; j++) {
            float4 wv = *reinterpret_cast<const float4*>(&ws[(obase + j) * 132 + d4 * 4]);
            acc[j] += xv.x * wv.x + xv.y * wv.y + xv.z * wv.z + xv.w * wv.w;
        }
    }
#pragma unroll
    for (int j = 0; j < 5; j++)
        g_z0[(size_t)node * OO + obase + j] = acc[j];
}

// hop 1 as gather: warp per dst node (needed set only).
// z1[n] = dinv[n]^2 * z0[n] + sum_{s in in(n)} dinv[s]*dinv[n]*z0[s]
__global__ void k_gather1(void) {
    int n = (blockIdx.x * blockDim.x + threadIdx.x) >> 5;
    if (n >= NN) return;
    if (!g_needed[n]) return;
    int lane = threadIdx.x & 31;
    float dn = g_dinv[n];
    const float* z0n = g_z0 + (size_t)n * OO;
    float acc1 = dn * dn * z0n[lane];
    float acc2 = (lane < OO - 32) ? dn * dn * z0n[32 + lane] : 0.f;
    int beg = g_off[n], end = g_off[n + 1];
    for (int i = beg; i < end; i++) {
        int s = g_csc_src[i];                 // warp-uniform -> broadcast
        float c = g_dinv[s] * dn;
        const float* zs = g_z0 + (size_t)s * OO;
        acc1 += c * zs[lane];
        if (lane < OO - 32) acc2 += c * zs[32 + lane];
    }
    float* z1n = g_z1 + (size_t)n * OO;
    z1n[lane] = acc1;
    if (lane < OO - 32) z1n[32 + lane] = acc2;
}

// hop 2 + bias + log_softmax fused: warp per cluster.
__global__ void k_gather2_lsm(const int* __restrict__ rep_idx, const float* __restrict__ b) {
    int c = (blockIdx.x * blockDim.x + threadIdx.x) >> 5;
    if (c >= CC) return;
    int lane = threadIdx.x & 31;
    int n = rep_idx[c];
    float dn = g_dinv[n];
    const float* z1n = g_z1 + (size_t)n * OO;
    float acc1 = dn * dn * z1n[lane];
    float acc2 = (lane < OO - 32) ? dn * dn * z1n[32 + lane] : 0.f;
    int beg = g_off[n], end = g_off[n + 1];
    for (int i = beg; i < end; i++) {
        int s = g_csc_src[i];
        float cf = g_dinv[s] * dn;
        const float* zs = g_z1 + (size_t)s * OO;
        acc1 += cf * zs[lane];
        if (lane < OO - 32) acc2 += cf * zs[32 + lane];
    }
    // + bias, log_softmax over 40 values (v1 on 32 lanes, v2 on first 8)
    float v1 = acc1 + b[lane];
    float v2 = (lane < OO - 32) ? (acc2 + b[32 + lane]) : -INFINITY;
    float m = fmaxf(v1, v2);
#pragma unroll
    for (int off = 16; off > 0; off >>= 1)
        m = fmaxf(m, __shfl_xor_sync(FULL_MASK, m, off));
    float s = expf(v1 - m) + ((lane < OO - 32) ? expf(v2 - m) : 0.f);
#pragma unroll
    for (int off = 16; off > 0; off >>= 1)
        s += __shfl_xor_sync(FULL_MASK, s, off);
    float ls = m + logf(s);
    float* lc = g_lsm + (size_t)c * OO;
    lc[lane] = v1 - ls;
    if (lane < OO - 32) lc[32 + lane] = v2 - ls;
}

// out[n][f] = lsm[cluster_index[n]][f]
__global__ void k_scatter(const int* __restrict__ cluster_index, float* __restrict__ out) {
    int idx = blockIdx.x * blockDim.x + threadIdx.x;
    if (idx >= NN * OO) return;
    int n = idx / OO;
    int f = idx - n * OO;
    out[idx] = g_lsm[(size_t)cluster_index[n] * OO + f];
}

// -------- launch ---------------------------------------------------------
extern "C" void kernel_launch(void* const* d_in, const int* in_sizes, int n_in,
                              void* d_out, int out_size) {
    const float* x       = (const float*)d_in[0];            // [N,128]
    const int*   eidx    = (const int*)d_in[1];              // [2,E] row-major
    const int*   cluster = (const int*)d_in[2];              // [N]
    const int*   rep_idx = (const int*)d_in[3];              // [C]
    const float* W       = (const float*)d_in[4];            // [40,128]
    const float* b       = (const float*)d_in[5];            // [40]
    float*       out     = (float*)d_out;                    // [N,40]

    const int* src = eidx;        // edge_index[0]
    const int* dst = eidx + EE;   // edge_index[1]

    const int T = 256;
    dim3 bN((NN + T - 1) / T);
    dim3 bE((EE + T - 1) / T);
    dim3 bC((CC + T - 1) / T);
    dim3 bNF((NN * OO + T - 1) / T);
    dim3 bNodeWarp((NN * 32 + T - 1) / T);   // warp per node
    dim3 bClWarp((CC * 32 + T - 1) / T);     // warp per cluster
    dim3 bGemm((NN + 31) / 32);

    k_init<<<bN, T>>>();
    k_mark_rep<<<bC, T>>>(rep_idx);
    k_count_mark<<<bE, T>>>(src, dst);
    k_scan<<<1, SCAN_T>>>();
    k_fill<<<bE, T>>>(src, dst);
    k_gemm<<<bGemm, T>>>(x, W);
    k_gather1<<<bNodeWarp, T>>>();
    k_gather2_lsm<<<bClWarp, T>>>(rep_idx, b);
    k_scatter<<<bNF, T>>>(cluster, out);
}

// round 5
// speedup vs baseline: 2.0095x; 1.9087x over previous
#include <cuda_runtime.h>
#include <math.h>

// Problem constants (fixed by the dataset)
#define NN   50000   // nodes
#define EE   800000  // edges
#define CC   5000    // clusters
#define DD   128     // in_features
#define OO   40      // out_features

#define FULL_MASK 0xffffffffu
#define ST 256
#define NBLK ((NN + ST - 1) / ST)    // 196 scan blocks

// -------- scratch (__device__ globals; only referenced from device code) --
__device__ int           g_cnt[NN];        // in-edge count (no self loop)
__device__ int           g_off[NN + 1];    // CSC offsets
__device__ int           g_pos[NN];        // placement cursor for fill
__device__ int           g_bsum[NBLK];     // per-block sums
__device__ int           g_boff[NBLK + 1]; // scanned block offsets
__device__ int           g_csc_src[EE];    // dst-sorted source indices
__device__ float         g_dinv[NN];
__device__ unsigned char g_is_rep[NN];
__device__ unsigned char g_needed[NN];
__device__ float         g_z0[NN * OO];    // projected features
__device__ float         g_z1[NN * OO];    // after hop 1
__device__ float         g_lsm[CC * OO];   // per-cluster log-softmax

// -------- kernels --------------------------------------------------------

__global__ void k_init(void) {
    int i = blockIdx.x * blockDim.x + threadIdx.x;
    if (i >= NN) return;
    g_cnt[i] = 0;
    g_is_rep[i] = 0;
    g_needed[i] = 0;
}

__global__ void k_mark_rep(const int* __restrict__ rep_idx) {
    int c = blockIdx.x * blockDim.x + threadIdx.x;
    if (c >= CC) return;
    int r = rep_idx[c];
    g_is_rep[r] = 1;
    g_needed[r] = 1;
}

// fused: count in-edges per dst + mark hop-1 needed set (srcs feeding reps)
__global__ void k_count_mark(const int* __restrict__ src, const int* __restrict__ dst) {
    int e = blockIdx.x * blockDim.x + threadIdx.x;
    if (e >= EE) return;
    int d = dst[e];
    atomicAdd(&g_cnt[d], 1);
    if (g_is_rep[d]) g_needed[src[e]] = 1;
}

// ---- 3-stage multi-block exclusive scan of g_cnt -------------------------

// stage 1: per-block exclusive scan; block sum to g_bsum
__global__ void k_scan1(void) {
    __shared__ int sh[ST];
    int tid = threadIdx.x;
    int i = blockIdx.x * ST + tid;
    int v = (i < NN) ? g_cnt[i] : 0;
    sh[tid] = v;
    __syncthreads();
#pragma unroll
    for (int off = 1; off < ST; off <<= 1) {
        int t = (tid >= off) ? sh[tid - off] : 0;
        __syncthreads();
        sh[tid] += t;
        __syncthreads();
    }
    if (i < NN) g_off[i] = sh[tid] - v;      // exclusive within block
    if (tid == ST - 1) g_bsum[blockIdx.x] = sh[tid];
}

// stage 2: single small block scans the 196 block sums (exclusive), total at end
__global__ void k_scan2(void) {
    __shared__ int sh[ST];
    int tid = threadIdx.x;
    int v = (tid < NBLK) ? g_bsum[tid] : 0;
    sh[tid] = v;
    __syncthreads();
#pragma unroll
    for (int off = 1; off < ST; off <<= 1) {
        int t = (tid >= off) ? sh[tid - off] : 0;
        __syncthreads();
        sh[tid] += t;
        __syncthreads();
    }
    if (tid < NBLK) g_boff[tid] = sh[tid] - v;
    if (tid == ST - 1) g_boff[NBLK] = sh[tid];   // grand total (== EE)
}

// stage 3: add block offsets; emit g_pos, g_dinv, g_off[NN]
__global__ void k_scan3(void) {
    int i = blockIdx.x * blockDim.x + threadIdx.x;
    if (i > NN) return;
    if (i == NN) { g_off[NN] = g_boff[NBLK]; return; }
    int o = g_off[i] + g_boff[i / ST];
    g_off[i] = o;
    g_pos[i] = o;
    g_dinv[i] = rsqrtf((float)(g_cnt[i] + 1));
}

// scatter edges into dst-sorted buckets (order within bucket is arbitrary)
__global__ void k_fill(const int* __restrict__ src, const int* __restrict__ dst) {
    int e = blockIdx.x * blockDim.x + threadIdx.x;
    if (e >= EE) return;
    int p = atomicAdd(&g_pos[dst[e]], 1);
    g_csc_src[p] = src[e];
}

// z0 = x @ W^T   (x:[N,128], W:[40,128])
__global__ void k_gemm(const float* __restrict__ x, const float* __restrict__ W) {
    __shared__ float ws[OO * 132];   // stride 132 floats (16B aligned, conflict-free)
    int tid = threadIdx.x;
    for (int idx = tid; idx < OO * DD; idx += 256) {
        int o = idx >> 7, d = idx & 127;
        ws[o * 132 + d] = W[idx];
    }
    __syncthreads();

    int ln = tid >> 3;         // node within block (0..31)
    int chunk = tid & 7;       // output chunk (0..7) -> outputs chunk*5..+4
    int node = blockIdx.x * 32 + ln;
    if (node >= NN) return;

    const float4* xr = reinterpret_cast<const float4*>(x + (size_t)node * DD);
    float acc[5] = {0.f, 0.f, 0.f, 0.f, 0.f};
    int obase = chunk * 5;
#pragma unroll
    for (int d4 = 0; d4 < DD / 4; d4++) {
        float4 xv = xr[d4];
#pragma unroll
        for (int j = 0; j < 5; j++) {
            float4 wv = *reinterpret_cast<const float4*>(&ws[(obase + j) * 132 + d4 * 4]);
            acc[j] += xv.x * wv.x + xv.y * wv.y + xv.z * wv.z + xv.w * wv.w;
        }
    }
#pragma unroll
    for (int j = 0; j < 5; j++)
        g_z0[(size_t)node * OO + obase + j] = acc[j];
}

// hop 1 as gather: warp per dst node (needed set only).
// z1[n] = dinv[n]^2 * z0[n] + sum_{s in in(n)} dinv[s]*dinv[n]*z0[s]
__global__ void k_gather1(void) {
    int n = (blockIdx.x * blockDim.x + threadIdx.x) >> 5;
    if (n >= NN) return;
    if (!g_needed[n]) return;
    int lane = threadIdx.x & 31;
    float dn = g_dinv[n];
    const float* z0n = g_z0 + (size_t)n * OO;
    float acc1 = dn * dn * z0n[lane];
    float acc2 = (lane < OO - 32) ? dn * dn * z0n[32 + lane] : 0.f;
    int beg = g_off[n], end = g_off[n + 1];
    for (int i = beg; i < end; i++) {
        int s = g_csc_src[i];                 // warp-uniform -> broadcast
        float c = g_dinv[s] * dn;
        const float* zs = g_z0 + (size_t)s * OO;
        acc1 += c * zs[lane];
        if (lane < OO - 32) acc2 += c * zs[32 + lane];
    }
    float* z1n = g_z1 + (size_t)n * OO;
    z1n[lane] = acc1;
    if (lane < OO - 32) z1n[32 + lane] = acc2;
}

// hop 2 + bias + log_softmax fused: warp per cluster.
__global__ void k_gather2_lsm(const int* __restrict__ rep_idx, const float* __restrict__ b) {
    int c = (blockIdx.x * blockDim.x + threadIdx.x) >> 5;
    if (c >= CC) return;
    int lane = threadIdx.x & 31;
    int n = rep_idx[c];
    float dn = g_dinv[n];
    const float* z1n = g_z1 + (size_t)n * OO;
    float acc1 = dn * dn * z1n[lane];
    float acc2 = (lane < OO - 32) ? dn * dn * z1n[32 + lane] : 0.f;
    int beg = g_off[n], end = g_off[n + 1];
    for (int i = beg; i < end; i++) {
        int s = g_csc_src[i];
        float cf = g_dinv[s] * dn;
        const float* zs = g_z1 + (size_t)s * OO;
        acc1 += cf * zs[lane];
        if (lane < OO - 32) acc2 += cf * zs[32 + lane];
    }
    // + bias, log_softmax over 40 values (v1 on 32 lanes, v2 on first 8)
    float v1 = acc1 + b[lane];
    float v2 = (lane < OO - 32) ? (acc2 + b[32 + lane]) : -INFINITY;
    float m = fmaxf(v1, v2);
#pragma unroll
    for (int off = 16; off > 0; off >>= 1)
        m = fmaxf(m, __shfl_xor_sync(FULL_MASK, m, off));
    float s = expf(v1 - m) + ((lane < OO - 32) ? expf(v2 - m) : 0.f);
#pragma unroll
    for (int off = 16; off > 0; off >>= 1)
        s += __shfl_xor_sync(FULL_MASK, s, off);
    float ls = m + logf(s);
    float* lc = g_lsm + (size_t)c * OO;
    lc[lane] = v1 - ls;
    if (lane < OO - 32) lc[32 + lane] = v2 - ls;
}

// out[n][f] = lsm[cluster_index[n]][f]
__global__ void k_scatter(const int* __restrict__ cluster_index, float* __restrict__ out) {
    int idx = blockIdx.x * blockDim.x + threadIdx.x;
    if (idx >= NN * OO) return;
    int n = idx / OO;
    int f = idx - n * OO;
    out[idx] = g_lsm[(size_t)cluster_index[n] * OO + f];
}

// -------- launch ---------------------------------------------------------
extern "C" void kernel_launch(void* const* d_in, const int* in_sizes, int n_in,
                              void* d_out, int out_size) {
    const float* x       = (const float*)d_in[0];            // [N,128]
    const int*   eidx    = (const int*)d_in[1];              // [2,E] row-major
    const int*   cluster = (const int*)d_in[2];              // [N]
    const int*   rep_idx = (const int*)d_in[3];              // [C]
    const float* W       = (const float*)d_in[4];            // [40,128]
    const float* b       = (const float*)d_in[5];            // [40]
    float*       out     = (float*)d_out;                    // [N,40]

    const int* src = eidx;        // edge_index[0]
    const int* dst = eidx + EE;   // edge_index[1]

    const int T = 256;
    dim3 bN((NN + T - 1) / T);
    dim3 bE((EE + T - 1) / T);
    dim3 bC((CC + T - 1) / T);
    dim3 bNF((NN * OO + T - 1) / T);
    dim3 bN1((NN + 1 + T - 1) / T);
    dim3 bNodeWarp((NN * 32 + T - 1) / T);   // warp per node
    dim3 bClWarp((CC * 32 + T - 1) / T);     // warp per cluster
    dim3 bGemm((NN + 31) / 32);

    k_init<<<bN, T>>>();
    k_mark_rep<<<bC, T>>>(rep_idx);
    k_count_mark<<<bE, T>>>(src, dst);
    k_scan1<<<NBLK, ST>>>();
    k_scan2<<<1, ST>>>();
    k_scan3<<<bN1, T>>>();
    k_fill<<<bE, T>>>(src, dst);
    k_gemm<<<bGemm, T>>>(x, W);
    k_gather1<<<bNodeWarp, T>>>();
    k_gather2_lsm<<<bClWarp, T>>>(rep_idx, b);
    k_scatter<<<bNF, T>>>(cluster, out);
}

// round 7
// speedup vs baseline: 2.5264x; 1.2572x over previous
#include <cuda_runtime.h>
#include <math.h>

// Problem constants (fixed by the dataset)
#define NN   50000   // nodes
#define EE   800000  // edges
#define CC   5000    // clusters
#define DD   128     // in_features
#define OO   40      // out_features
#define Q10  (OO / 4)   // 10 float4 quads per row

#define FULL_MASK 0xffffffffu
#define ST 256
#define NBLK ((NN + ST - 1) / ST)    // 196 scan blocks

typedef unsigned long long u64;

// -------- scratch (__device__ globals; referenced only from device code) --
// g_cnt relies on BSS zero-init at load; k_scatter re-zeros it every call.
__device__ int           g_cnt[NN];
__device__ int           g_off[NN + 1];
__device__ int           g_pos[NN];
__device__ int           g_bsum[NBLK];
__device__ int           g_boff[NBLK + 1];
__device__ int2          g_csc[EE];        // {src, __float_as_int(dinv[src])}
__device__ float         g_dinv[NN];
__device__ unsigned char g_needed[NN];
__device__ float4        g_z0[NN * Q10];   // projected features
__device__ float4        g_z1[NN * Q10];   // after hop 1
__device__ float4        g_lsm[CC * Q10];  // per-cluster log-softmax

// packed dual-FMA (sm_100+): d = a*b + c elementwise on 2 packed f32
__device__ __forceinline__ u64 fma2(u64 a, u64 b, u64 c) {
    u64 d;
    asm("fma.rn.f32x2 %0, %1, %2, %3;" : "=l"(d) : "l"(a), "l"(b), "l"(c));
    return d;
}
__device__ __forceinline__ float pairsum(u64 v) {
    return __uint_as_float((unsigned)(v & 0xffffffffu)) +
           __uint_as_float((unsigned)(v >> 32));
}

// -------- kernels --------------------------------------------------------

// count in-edges per dst (int4-vectorized; EE % 4 == 0)
__global__ void k_count(const int* __restrict__ dst) {
    int e4 = blockIdx.x * blockDim.x + threadIdx.x;
    if (e4 >= EE / 4) return;
    int4 d = reinterpret_cast<const int4*>(dst)[e4];
    atomicAdd(&g_cnt[d.x], 1);
    atomicAdd(&g_cnt[d.y], 1);
    atomicAdd(&g_cnt[d.z], 1);
    atomicAdd(&g_cnt[d.w], 1);
}

// ---- 3-stage multi-block exclusive scan of g_cnt -------------------------
__global__ void k_scan1(void) {
    __shared__ int sh[ST];
    int tid = threadIdx.x;
    int i = blockIdx.x * ST + tid;
    int v = (i < NN) ? g_cnt[i] : 0;
    sh[tid] = v;
    __syncthreads();
#pragma unroll
    for (int off = 1; off < ST; off <<= 1) {
        int t = (tid >= off) ? sh[tid - off] : 0;
        __syncthreads();
        sh[tid] += t;
        __syncthreads();
    }
    if (i < NN) g_off[i] = sh[tid] - v;
    if (tid == ST - 1) g_bsum[blockIdx.x] = sh[tid];
}

__global__ void k_scan2(void) {
    __shared__ int sh[ST];
    int tid = threadIdx.x;
    int v = (tid < NBLK) ? g_bsum[tid] : 0;
    sh[tid] = v;
    __syncthreads();
#pragma unroll
    for (int off = 1; off < ST; off <<= 1) {
        int t = (tid >= off) ? sh[tid - off] : 0;
        __syncthreads();
        sh[tid] += t;
        __syncthreads();
    }
    if (tid < NBLK) g_boff[tid] = sh[tid] - v;
    if (tid == ST - 1) g_boff[NBLK] = sh[tid];
}

// stage 3: finalize offsets; emit pos cursor, dinv, clear needed mask
__global__ void k_scan3(void) {
    int i = blockIdx.x * blockDim.x + threadIdx.x;
    if (i > NN) return;
    if (i == NN) { g_off[NN] = g_boff[NBLK]; return; }
    int o = g_off[i] + g_boff[i / ST];
    g_off[i] = o;
    g_pos[i] = o;
    g_dinv[i] = rsqrtf((float)(g_cnt[i] + 1));
    g_needed[i] = 0;
}

// scatter edges into dst buckets; pack src + dinv[src] (dinv ready after scan3)
__global__ void k_fill(const int* __restrict__ src, const int* __restrict__ dst) {
    int e4 = blockIdx.x * blockDim.x + threadIdx.x;
    if (e4 >= EE / 4) return;
    int4 s = reinterpret_cast<const int4*>(src)[e4];
    int4 d = reinterpret_cast<const int4*>(dst)[e4];
    int p;
    p = atomicAdd(&g_pos[d.x], 1); g_csc[p] = make_int2(s.x, __float_as_int(g_dinv[s.x]));
    p = atomicAdd(&g_pos[d.y], 1); g_csc[p] = make_int2(s.y, __float_as_int(g_dinv[s.y]));
    p = atomicAdd(&g_pos[d.z], 1); g_csc[p] = make_int2(s.z, __float_as_int(g_dinv[s.z]));
    p = atomicAdd(&g_pos[d.w], 1); g_csc[p] = make_int2(s.w, __float_as_int(g_dinv[s.w]));
}

// mark hop-1 needed set from rep in-edges (warp per cluster, ~80k edges total)
__global__ void k_mark_needed(const int* __restrict__ rep_idx) {
    int c = (blockIdx.x * blockDim.x + threadIdx.x) >> 5;
    if (c >= CC) return;
    int lane = threadIdx.x & 31;
    int r = rep_idx[c];
    if (lane == 0) g_needed[r] = 1;
    int beg = g_off[r], end = g_off[r + 1];
    for (int i = beg + lane; i < end; i += 32)
        g_needed[g_csc[i].x] = 1;
}

// z0 = x @ W^T. Block = 256 threads -> 128 nodes. Thread: 4 nodes x 5 outs,
// packed f32x2 FMAs; W in smem, amortized 4x across the node tile.
__global__ void k_gemm(const float* __restrict__ x, const float* __restrict__ W) {
    __shared__ __align__(16) float ws[OO * 132];   // row stride 132 floats (528B, 16B-mult)
    int tid = threadIdx.x;
    for (int idx = tid; idx < OO * DD; idx += 256) {
        int o = idx >> 7, d = idx & 127;
        ws[o * 132 + d] = W[idx];
    }
    __syncthreads();

    int ng = tid >> 3;         // 0..31 node group
    int chunk = tid & 7;       // 0..7 -> outputs chunk*5..+4
    int n0 = blockIdx.x * 128 + ng * 4;
    if (n0 >= NN) return;
    int obase = chunk * 5;

    const ulonglong2* xr[4];
    bool valid[4];
#pragma unroll
    for (int j = 0; j < 4; j++) {
        valid[j] = (n0 + j) < NN;
        int nn = valid[j] ? (n0 + j) : n0;
        xr[j] = reinterpret_cast<const ulonglong2*>(x + (size_t)nn * DD);
    }
    const ulonglong2* wsu = reinterpret_cast<const ulonglong2*>(ws);  // row stride 33

    u64 acc[4][5];
#pragma unroll
    for (int j = 0; j < 4; j++)
#pragma unroll
        for (int o = 0; o < 5; o++) acc[j][o] = 0ull;

#pragma unroll 4
    for (int d4 = 0; d4 < DD / 4; d4++) {
        ulonglong2 xp[4];
#pragma unroll
        for (int j = 0; j < 4; j++) xp[j] = xr[j][d4];
#pragma unroll
        for (int o = 0; o < 5; o++) {
            ulonglong2 wp = wsu[(obase + o) * 33 + d4];
#pragma unroll
            for (int j = 0; j < 4; j++) {
                acc[j][o] = fma2(xp[j].x, wp.x, acc[j][o]);
                acc[j][o] = fma2(xp[j].y, wp.y, acc[j][o]);
            }
        }
    }

    float* z0 = reinterpret_cast<float*>(g_z0);
#pragma unroll
    for (int j = 0; j < 4; j++) {
        if (!valid[j]) continue;
        float* row = z0 + (size_t)(n0 + j) * OO + obase;
#pragma unroll
        for (int o = 0; o < 5; o++) row[o] = pairsum(acc[j][o]);
    }
}

// hop 1 gather (needed nodes only): thread per (node, float4 quad)
__global__ void k_gather1(void) {
    int idx = blockIdx.x * blockDim.x + threadIdx.x;
    if (idx >= NN * Q10) return;
    int n = idx / Q10;
    int q = idx - n * Q10;
    if (!g_needed[n]) return;
    float dn = g_dinv[n];
    float w = dn * dn;
    float4 a = g_z0[(size_t)n * Q10 + q];
    float4 acc = make_float4(w * a.x, w * a.y, w * a.z, w * a.w);
    int beg = g_off[n], end = g_off[n + 1];
    int i = beg;
    for (; i + 1 < end; i += 2) {
        int2 e0 = g_csc[i], e1 = g_csc[i + 1];
        float4 v0 = g_z0[(size_t)e0.x * Q10 + q];
        float4 v1 = g_z0[(size_t)e1.x * Q10 + q];
        float c0 = __int_as_float(e0.y) * dn;
        float c1 = __int_as_float(e1.y) * dn;
        acc.x += c0 * v0.x + c1 * v1.x;
        acc.y += c0 * v0.y + c1 * v1.y;
        acc.z += c0 * v0.z + c1 * v1.z;
        acc.w += c0 * v0.w + c1 * v1.w;
    }
    if (i < end) {
        int2 e0 = g_csc[i];
        float4 v0 = g_z0[(size_t)e0.x * Q10 + q];
        float c0 = __int_as_float(e0.y) * dn;
        acc.x += c0 * v0.x; acc.y += c0 * v0.y;
        acc.z += c0 * v0.z; acc.w += c0 * v0.w;
    }
    g_z1[(size_t)n * Q10 + q] = acc;
}

// hop 2 + bias + log_softmax fused: warp per cluster
__global__ void k_gather2_lsm(const int* __restrict__ rep_idx, const float* __restrict__ b) {
    int c = (blockIdx.x * blockDim.x + threadIdx.x) >> 5;
    if (c >= CC) return;
    int lane = threadIdx.x & 31;
    int n = rep_idx[c];
    float dn = g_dinv[n];
    const float* z1 = reinterpret_cast<const float*>(g_z1);
    const float* z1n = z1 + (size_t)n * OO;
    float acc1 = dn * dn * z1n[lane];
    float acc2 = (lane < OO - 32) ? dn * dn * z1n[32 + lane] : 0.f;
    int beg = g_off[n], end = g_off[n + 1];
    for (int i = beg; i < end; i++) {
        int2 e = g_csc[i];
        float cf = __int_as_float(e.y) * dn;
        const float* zs = z1 + (size_t)e.x * OO;
        acc1 += cf * zs[lane];
        if (lane < OO - 32) acc2 += cf * zs[32 + lane];
    }
    float v1 = acc1 + b[lane];
    float v2 = (lane < OO - 32) ? (acc2 + b[32 + lane]) : -INFINITY;
    float m = fmaxf(v1, v2);
#pragma unroll
    for (int off = 16; off > 0; off >>= 1)
        m = fmaxf(m, __shfl_xor_sync(FULL_MASK, m, off));
    float s = expf(v1 - m) + ((lane < OO - 32) ? expf(v2 - m) : 0.f);
#pragma unroll
    for (int off = 16; off > 0; off >>= 1)
        s += __shfl_xor_sync(FULL_MASK, s, off);
    float ls = m + logf(s);
    float* lc = reinterpret_cast<float*>(g_lsm) + (size_t)c * OO;
    lc[lane] = v1 - ls;
    if (lane < OO - 32) lc[32 + lane] = v2 - ls;
}

// out[n] = lsm[cluster[n]] (float4); also reset g_cnt for the next call
__global__ void k_scatter(const int* __restrict__ cluster_index, float4* __restrict__ out) {
    int idx = blockIdx.x * blockDim.x + threadIdx.x;
    if (idx >= NN * Q10) return;
    int n = idx / Q10;
    int q = idx - n * Q10;
    if (q == 0) g_cnt[n] = 0;
    out[idx] = g_lsm[(size_t)cluster_index[n] * Q10 + q];
}

// -------- launch ---------------------------------------------------------
extern "C" void kernel_launch(void* const* d_in, const int* in_sizes, int n_in,
                              void* d_out, int out_size) {
    const float* x       = (const float*)d_in[0];            // [N,128]
    const int*   eidx    = (const int*)d_in[1];              // [2,E] row-major
    const int*   cluster = (const int*)d_in[2];              // [N]
    const int*   rep_idx = (const int*)d_in[3];              // [C]
    const float* W       = (const float*)d_in[4];            // [40,128]
    const float* b       = (const float*)d_in[5];            // [40]
    float4*      out     = (float4*)d_out;                   // [N,40]

    const int* src = eidx;        // edge_index[0]
    const int* dst = eidx + EE;   // edge_index[1]

    const int T = 256;
    dim3 bE4((EE / 4 + T - 1) / T);
    dim3 bN1((NN + 1 + T - 1) / T);
    dim3 bNQ((NN * Q10 + T - 1) / T);
    dim3 bClWarp((CC * 32 + T - 1) / T);
    dim3 bGemm((NN + 127) / 128);

    k_count<<<bE4, T>>>(dst);
    k_scan1<<<NBLK, ST>>>();
    k_scan2<<<1, ST>>>();
    k_scan3<<<bN1, T>>>();
    k_fill<<<bE4, T>>>(src, dst);
    k_mark_needed<<<bClWarp, T>>>(rep_idx);
    k_gemm<<<bGemm, T>>>(x, W);
    k_gather1<<<bNQ, T>>>();
    k_gather2_lsm<<<bClWarp, T>>>(rep_idx, b);
    k_scatter<<<bNQ, T>>>(cluster, out);
}

// round 10
// speedup vs baseline: 2.6812x; 1.0613x over previous
#include <cuda_runtime.h>
#include <math.h>

// Problem constants (fixed by the dataset)
#define NN   50000   // nodes
#define EE   800000  // edges
#define CC   5000    // clusters
#define DD   128     // in_features
#define OO   40      // out_features
#define Q10  (OO / 4)   // 10 float4 quads per row

#define FULL_MASK 0xffffffffu

typedef unsigned long long u64;

// role-split grid for kernel A
#define NB_CNT  ((EE / 4 + 255) / 256)          // 782 blocks: degree count
#define NB_GEMM ((NN + 127) / 128)              // 391 blocks: projection GEMM
#define NB_REP  ((CC + 255) / 256)              // 20 blocks: rep marking
#define NB_A    (NB_CNT + NB_GEMM + NB_REP)

// -------- scratch (__device__ globals; referenced only from device code) --
// Cleared state relies on BSS zero-init at load; k_scatter re-clears each call.
__device__ int           g_cnt[NN];
__device__ int           g_off[NN];         // bucket base (atomic-assigned)
__device__ int           g_pos[NN];         // fill cursor
__device__ int           g_total;           // bump allocator for buckets
__device__ int2          g_csc[EE];         // {src, __float_as_int(dinv[src])}
__device__ float         g_dinv[NN];
__device__ unsigned char g_is_rep[NN];
__device__ unsigned char g_needed[NN];
__device__ float4        g_z0[NN * Q10];    // projected features
__device__ float4        g_z1[NN * Q10];    // after hop 1
__device__ float4        g_lsm[CC * Q10];   // per-cluster log-softmax

// packed dual-FMA (sm_100+): d = a*b + c elementwise on 2 packed f32
__device__ __forceinline__ u64 fma2(u64 a, u64 b, u64 c) {
    u64 d;
    asm("fma.rn.f32x2 %0, %1, %2, %3;" : "=l"(d) : "l"(a), "l"(b), "l"(c));
    return d;
}
__device__ __forceinline__ float pairsum(u64 v) {
    return __uint_as_float((unsigned)(v & 0xffffffffu)) +
           __uint_as_float((unsigned)(v >> 32));
}

// ---- kernel A: three independent roles fused into one launch ------------
// role 0 (blocks [0, NB_CNT)):            in-degree count over dst (int4)
// role 1 (blocks [NB_CNT, NB_CNT+GEMM)):  z0 = x @ W^T
// role 2 (rest):                          mark is_rep / needed for reps
__global__ void kA(const int* __restrict__ dst, const int* __restrict__ rep_idx,
                   const float* __restrict__ x, const float* __restrict__ W) {
    __shared__ __align__(16) float ws[OO * 132];   // only used by role 1
    int blk = blockIdx.x;
    int tid = threadIdx.x;

    if (blk < NB_CNT) {                    // ---- degree count ----
        int e4 = blk * 256 + tid;
        if (e4 >= EE / 4) return;
        int4 d = reinterpret_cast<const int4*>(dst)[e4];
        atomicAdd(&g_cnt[d.x], 1);
        atomicAdd(&g_cnt[d.y], 1);
        atomicAdd(&g_cnt[d.z], 1);
        atomicAdd(&g_cnt[d.w], 1);
        return;
    }
    if (blk >= NB_CNT + NB_GEMM) {         // ---- rep marking ----
        int c = (blk - NB_CNT - NB_GEMM) * 256 + tid;
        if (c >= CC) return;
        int r = rep_idx[c];
        g_is_rep[r] = 1;
        g_needed[r] = 1;
        return;
    }

    // ---- projection GEMM: 128 nodes/block, 4 nodes x 5 outs per thread ----
    int gblk = blk - NB_CNT;
    for (int idx = tid; idx < OO * DD; idx += 256) {
        int o = idx >> 7, d = idx & 127;
        ws[o * 132 + d] = W[idx];
    }
    __syncthreads();

    int ng = tid >> 3;
    int chunk = tid & 7;
    int n0 = gblk * 128 + ng * 4;
    if (n0 >= NN) return;
    int obase = chunk * 5;

    const ulonglong2* xr[4];
    bool valid[4];
#pragma unroll
    for (int j = 0; j < 4; j++) {
        valid[j] = (n0 + j) < NN;
        int nn = valid[j] ? (n0 + j) : n0;
        xr[j] = reinterpret_cast<const ulonglong2*>(x + (size_t)nn * DD);
    }
    const ulonglong2* wsu = reinterpret_cast<const ulonglong2*>(ws);  // row stride 33

    u64 acc[4][5];
#pragma unroll
    for (int j = 0; j < 4; j++)
#pragma unroll
        for (int o = 0; o < 5; o++) acc[j][o] = 0ull;

#pragma unroll 4
    for (int d4 = 0; d4 < DD / 4; d4++) {
        ulonglong2 xp[4];
#pragma unroll
        for (int j = 0; j < 4; j++) xp[j] = xr[j][d4];
#pragma unroll
        for (int o = 0; o < 5; o++) {
            ulonglong2 wp = wsu[(obase + o) * 33 + d4];
#pragma unroll
            for (int j = 0; j < 4; j++) {
                acc[j][o] = fma2(xp[j].x, wp.x, acc[j][o]);
                acc[j][o] = fma2(xp[j].y, wp.y, acc[j][o]);
            }
        }
    }

    float* z0 = reinterpret_cast<float*>(g_z0);
#pragma unroll
    for (int j = 0; j < 4; j++) {
        if (!valid[j]) continue;
        float* row = z0 + (size_t)(n0 + j) * OO + obase;
#pragma unroll
        for (int o = 0; o < 5; o++) row[o] = pairsum(acc[j][o]);
    }
}

// prep: bucket base via bump allocator (no scan), fill cursor, dinv
__global__ void k_prep(void) {
    int i = blockIdx.x * blockDim.x + threadIdx.x;
    if (i >= NN) return;
    int c = g_cnt[i];
    int o = atomicAdd(&g_total, c);
    g_off[i] = o;
    g_pos[i] = o;
    g_dinv[i] = rsqrtf((float)(c + 1));
}

// fill CSC buckets; pack dinv[src]; mark hop-1 needed set (srcs feeding reps)
__global__ void k_fill(const int* __restrict__ src, const int* __restrict__ dst) {
    int e4 = blockIdx.x * blockDim.x + threadIdx.x;
    if (e4 >= EE / 4) return;
    int4 s = reinterpret_cast<const int4*>(src)[e4];
    int4 d = reinterpret_cast<const int4*>(dst)[e4];
    int p;
    p = atomicAdd(&g_pos[d.x], 1); g_csc[p] = make_int2(s.x, __float_as_int(g_dinv[s.x]));
    p = atomicAdd(&g_pos[d.y], 1); g_csc[p] = make_int2(s.y, __float_as_int(g_dinv[s.y]));
    p = atomicAdd(&g_pos[d.z], 1); g_csc[p] = make_int2(s.z, __float_as_int(g_dinv[s.z]));
    p = atomicAdd(&g_pos[d.w], 1); g_csc[p] = make_int2(s.w, __float_as_int(g_dinv[s.w]));
    if (g_is_rep[d.x]) g_needed[s.x] = 1;
    if (g_is_rep[d.y]) g_needed[s.y] = 1;
    if (g_is_rep[d.z]) g_needed[s.z] = 1;
    if (g_is_rep[d.w]) g_needed[s.w] = 1;
}

// hop 1 gather (needed nodes only): thread per (node, float4 quad)
__global__ void k_gather1(void) {
    int idx = blockIdx.x * blockDim.x + threadIdx.x;
    if (idx >= NN * Q10) return;
    int n = idx / Q10;
    int q = idx - n * Q10;
    if (!g_needed[n]) return;
    float dn = g_dinv[n];
    float w = dn * dn;
    float4 a = g_z0[(size_t)n * Q10 + q];
    float4 acc = make_float4(w * a.x, w * a.y, w * a.z, w * a.w);
    int beg = g_off[n], end = beg + g_cnt[n];
    int i = beg;
    for (; i + 1 < end; i += 2) {
        int2 e0 = g_csc[i], e1 = g_csc[i + 1];
        float4 v0 = g_z0[(size_t)e0.x * Q10 + q];
        float4 v1 = g_z0[(size_t)e1.x * Q10 + q];
        float c0 = __int_as_float(e0.y) * dn;
        float c1 = __int_as_float(e1.y) * dn;
        acc.x += c0 * v0.x + c1 * v1.x;
        acc.y += c0 * v0.y + c1 * v1.y;
        acc.z += c0 * v0.z + c1 * v1.z;
        acc.w += c0 * v0.w + c1 * v1.w;
    }
    if (i < end) {
        int2 e0 = g_csc[i];
        float4 v0 = g_z0[(size_t)e0.x * Q10 + q];
        float c0 = __int_as_float(e0.y) * dn;
        acc.x += c0 * v0.x; acc.y += c0 * v0.y;
        acc.z += c0 * v0.z; acc.w += c0 * v0.w;
    }
    g_z1[(size_t)n * Q10 + q] = acc;
}

// hop 2 + bias + log_softmax fused: warp per cluster
__global__ void k_gather2_lsm(const int* __restrict__ rep_idx, const float* __restrict__ b) {
    int c = (blockIdx.x * blockDim.x + threadIdx.x) >> 5;
    if (c >= CC) return;
    int lane = threadIdx.x & 31;
    int n = rep_idx[c];
    float dn = g_dinv[n];
    const float* z1 = reinterpret_cast<const float*>(g_z1);
    const float* z1n = z1 + (size_t)n * OO;
    float acc1 = dn * dn * z1n[lane];
    float acc2 = (lane < OO - 32) ? dn * dn * z1n[32 + lane] : 0.f;
    int beg = g_off[n], end = beg + g_cnt[n];
    for (int i = beg; i < end; i++) {
        int2 e = g_csc[i];
        float cf = __int_as_float(e.y) * dn;
        const float* zs = z1 + (size_t)e.x * OO;
        acc1 += cf * zs[lane];
        if (lane < OO - 32) acc2 += cf * zs[32 + lane];
    }
    float v1 = acc1 + b[lane];
    float v2 = (lane < OO - 32) ? (acc2 + b[32 + lane]) : -INFINITY;
    float m = fmaxf(v1, v2);
#pragma unroll
    for (int off = 16; off > 0; off >>= 1)
        m = fmaxf(m, __shfl_xor_sync(FULL_MASK, m, off));
    float s = expf(v1 - m) + ((lane < OO - 32) ? expf(v2 - m) : 0.f);
#pragma unroll
    for (int off = 16; off > 0; off >>= 1)
        s += __shfl_xor_sync(FULL_MASK, s, off);
    float ls = m + logf(s);
    float* lc = reinterpret_cast<float*>(g_lsm) + (size_t)c * OO;
    lc[lane] = v1 - ls;
    if (lane < OO - 32) lc[32 + lane] = v2 - ls;
}

// out[n] = lsm[cluster[n]] (float4); also reset all scratch for next call
__global__ void k_scatter(const int* __restrict__ cluster_index, float4* __restrict__ out) {
    int idx = blockIdx.x * blockDim.x + threadIdx.x;
    if (idx >= NN * Q10) return;
    int n = idx / Q10;
    int q = idx - n * Q10;
    if (q == 0) {                 // one thread per node clears scratch
        g_cnt[n] = 0;
        g_needed[n] = 0;
        g_is_rep[n] = 0;
        if (n == 0) g_total = 0;
    }
    out[idx] = g_lsm[(size_t)cluster_index[n] * Q10 + q];
}

// -------- launch ---------------------------------------------------------
extern "C" void kernel_launch(void* const* d_in, const int* in_sizes, int n_in,
                              void* d_out, int out_size) {
    const float* x       = (const float*)d_in[0];            // [N,128]
    const int*   eidx    = (const int*)d_in[1];              // [2,E] row-major
    const int*   cluster = (const int*)d_in[2];              // [N]
    const int*   rep_idx = (const int*)d_in[3];              // [C]
    const float* W       = (const float*)d_in[4];            // [40,128]
    const float* b       = (const float*)d_in[5];            // [40]
    float4*      out     = (float4*)d_out;                   // [N,40]

    const int* src = eidx;        // edge_index[0]
    const int* dst = eidx + EE;   // edge_index[1]

    const int T = 256;
    dim3 bE4((EE / 4 + T - 1) / T);
    dim3 bN((NN + T - 1) / T);
    dim3 bNQ((NN * Q10 + T - 1) / T);
    dim3 bClWarp((CC * 32 + T - 1) / T);

    kA<<<NB_A, T>>>(dst, rep_idx, x, W);
    k_prep<<<bN, T>>>();
    k_fill<<<bE4, T>>>(src, dst);
    k_gather1<<<bNQ, T>>>();
    k_gather2_lsm<<<bClWarp, T>>>(rep_idx, b);
    k_scatter<<<bNQ, T>>>(cluster, out);
}